// round 5
// baseline (speedup 1.0000x reference)
#include <cuda_runtime.h>

// ---------------- Problem constants ----------------
#define NBOX 8000          // 5 anchors * 40 * 40
#define HW 40
#define NCLS 20
#define CHSTRIDE (HW*HW)   // 1600 floats between channels
#define STRIDEPX 8.0f      // 320 / 40
#define IOU_THR 0.5f

// rank-sort chunking
#define JC 16
#define CHUNK (NBOX/JC)    // 500
#define IGROUPS 32         // 32 * 256 = 8192 >= 8000

#define MMASK 384          // mask-matrix fast-path capacity (expected M ~ 200)
#define NWMAX 12           // 384/32 words per mask row
#define CAP 768            // shared box capacity (mid path)

// ---------------- Scratch (device globals, no allocation) ----------------
__device__ float              d_dec6[NBOX * 6];       // cx,cy,w,h,conf,cls (original index order)
__device__ unsigned long long d_key[NBOX];            // sort key: (~bits(conf))<<32 | idx
__device__ unsigned char      d_code[NBOX];           // valid ? cls : 255
__device__ unsigned           d_partial[JC * NBOX];   // packed: rank | cls_rank<<16
__device__ int                d_ord[NBOX];            // global rank -> original index
__device__ int                d_cand[NCLS * NBOX];    // per-class ranks, SORTED by construction
__device__ int                d_cnt[NCLS];

// ---------------- K1: decode (+ zero output) ----------------
__global__ void k_decode(const float* __restrict__ x, const float* __restrict__ anchors,
                         float* __restrict__ out) {
    int i = blockIdx.x * blockDim.x + threadIdx.x;
    int stride = gridDim.x * blockDim.x;
    for (int t = i; t < NBOX * 6; t += stride) out[t] = 0.0f;   // zero output (poisoned pre-run)
    if (i >= NBOX) return;

    int a   = i / (HW * HW);
    int rem = i - a * (HW * HW);
    int gy  = rem / HW;
    int gx  = rem - gy * HW;
    int base = ((a * 25) * HW + gy) * HW + gx;

    float t0 = x[base + 0 * CHSTRIDE];
    float t1 = x[base + 1 * CHSTRIDE];
    float t2 = x[base + 2 * CHSTRIDE];
    float t3 = x[base + 3 * CHSTRIDE];
    float t4 = x[base + 4 * CHSTRIDE];

    float tx   = 1.0f / (1.0f + expf(-t0));
    float ty   = 1.0f / (1.0f + expf(-t1));
    float conf = 1.0f / (1.0f + expf(-t4));

    float aw = anchors[a * 2 + 0];
    float ah = anchors[a * 2 + 1];

    float bx = (tx + (float)gx) * STRIDEPX;
    float by = (ty + (float)gy) * STRIDEPX;
    float bw = expf(t2) * aw * STRIDEPX;
    float bh = expf(t3) * ah * STRIDEPX;

    // argmax over class logits (sigmoid monotone; '>' keeps first occurrence like jnp.argmax)
    float best = x[base + 5 * CHSTRIDE];
    int bc = 0;
#pragma unroll
    for (int c = 1; c < NCLS; c++) {
        float t = x[base + (5 + c) * CHSTRIDE];
        if (t > best) { best = t; bc = c; }
    }

    d_dec6[i * 6 + 0] = bx;
    d_dec6[i * 6 + 1] = by;
    d_dec6[i * 6 + 2] = bw;
    d_dec6[i * 6 + 3] = bh;
    d_dec6[i * 6 + 4] = conf;
    d_dec6[i * 6 + 5] = (float)bc;

    // conf in (0,1) positive -> float bits monotone. Descending conf, tie -> ascending idx.
    unsigned u = __float_as_uint(conf);
    d_key[i] = ((unsigned long long)(~u) << 32) | (unsigned long long)(unsigned)i;

    // conf > 0.5  <=>  logit > 0
    d_code[i] = (t4 > 0.0f) ? (unsigned char)bc : (unsigned char)255;
}

// ---------------- K2: chunked rank (global + same-class) ----------------
__global__ void k_rank() {
    __shared__ unsigned long long sk[CHUNK];
    __shared__ unsigned char     sc[CHUNK];
    if (blockIdx.x == 0 && threadIdx.x < NCLS) d_cnt[threadIdx.x] = 0;
    int g = blockIdx.x / JC;
    int c = blockIdx.x - g * JC;
    for (int t = threadIdx.x; t < CHUNK; t += 256) {
        sk[t] = d_key[c * CHUNK + t];
        sc[t] = d_code[c * CHUNK + t];
    }
    __syncthreads();
    int i = g * 256 + threadIdx.x;
    if (i < NBOX) {
        unsigned long long my = d_key[i];
        unsigned char myc = d_code[i];
        int cnt = 0, cc = 0;
#pragma unroll 10
        for (int j = 0; j < CHUNK; j++) {
            bool lt = sk[j] < my;
            cnt += lt ? 1 : 0;
            cc  += (lt && sc[j] == myc) ? 1 : 0;
        }
        d_partial[c * NBOX + i] = (unsigned)cnt | ((unsigned)cc << 16);
    }
}

// ---------------- K2b: scatter -> permutation + sorted per-class slots ----------------
__global__ void k_scatter() {
    int i = blockIdx.x * blockDim.x + threadIdx.x;
    if (i >= NBOX) return;
    unsigned s = 0;
#pragma unroll
    for (int c = 0; c < JC; c++) s += d_partial[c * NBOX + i];
    int r  = (int)(s & 0xffffu);   // global rank (unique)
    int rc = (int)(s >> 16);       // rank among same-class valid (unique within class)
    d_ord[r] = i;
    unsigned char code = d_code[i];
    if (code != (unsigned char)255) {
        d_cand[(int)code * NBOX + rc] = r;   // sorted by construction
        atomicAdd(&d_cnt[code], 1);
    }
}

// helper: box coords for global rank r
__device__ __forceinline__ void load_box_r(int r, float& x1, float& y1,
                                           float& x2, float& y2, float& ar) {
    int i = d_ord[r];
    float cx = d_dec6[i * 6 + 0];
    float cy = d_dec6[i * 6 + 1];
    float w  = d_dec6[i * 6 + 2];
    float h  = d_dec6[i * 6 + 3];
    x1 = cx - 0.5f * w; y1 = cy - 0.5f * h;
    x2 = cx + 0.5f * w; y2 = cy + 0.5f * h;
    ar = fabsf((x2 - x1) * (y2 - y1));
}

__device__ __forceinline__ void emit_row(float* out, int r) {
    int i = d_ord[r];
#pragma unroll
    for (int k = 0; k < 6; k++) out[6 * r + k] = d_dec6[i * 6 + k];
}

// ---------------- K3: per-class NMS (candidates pre-sorted) + output rows ----------------
__global__ void k_nms(float* __restrict__ out) {
    __shared__ int      sps[CAP];
    __shared__ float    sx1[CAP], sy1[CAP], sx2[CAP], sy2[CAP], sar[CAP];
    __shared__ unsigned skw[NWMAX];
    __shared__ unsigned char ubuf[MMASK * NWMAX * 4];   // union: mask matrix / keep bytes
    unsigned* smask = (unsigned*)ubuf;                  // fast path
    unsigned char* skbyte = ubuf;                       // mid/global paths

    int c    = blockIdx.x;
    int tid  = threadIdx.x;
    int lane = tid & 31;
    int M    = d_cnt[c];
    if (M == 0) return;

    if (M <= CAP) {
        for (int t = tid; t < M; t += 512) {
            int r = d_cand[c * NBOX + t];
            sps[t] = r;
            float x1, y1, x2, y2, ar;
            load_box_r(r, x1, y1, x2, y2, ar);
            sx1[t] = x1; sy1[t] = y1; sx2[t] = x2; sy2[t] = y2; sar[t] = ar;
        }
        __syncthreads();

        if (M <= MMASK) {
            // ---- fast path: parallel suppression-mask matrix ----
            int nw = (M + 31) >> 5;
            for (int task = tid; task < M * NWMAX; task += 512) {
                int i  = task / NWMAX;
                int wq = task - i * NWMAX;
                unsigned bits = 0;
                if (wq < nw && (wq * 32 + 31) > i) {
                    float xi1 = sx1[i], yi1 = sy1[i], xi2 = sx2[i], yi2 = sy2[i], ai = sar[i];
                    int j0 = wq * 32;
                    int jend = min(j0 + 32, M);
#pragma unroll 4
                    for (int j = max(j0, i + 1); j < jend; j++) {
                        float iw = fmaxf(fminf(xi2, sx2[j]) - fmaxf(xi1, sx1[j]), 0.0f);
                        float ih = fmaxf(fminf(yi2, sy2[j]) - fmaxf(yi1, sy1[j]), 0.0f);
                        float inter = iw * ih;
                        float iou = inter / (ai + sar[j] - inter + 1e-6f);
                        if (iou >= IOU_THR) bits |= 1u << (j - j0);
                    }
                }
                smask[task] = bits;
            }
            __syncthreads();

            // ---- serial greedy sweep, warp 0, skipping suppressed bits ----
            if (tid < 32) {
                unsigned kw = 0;
                if (lane < NWMAX) {
                    int lo = lane * 32;
                    if (lo < M) {
                        int rem = M - lo;
                        kw = (rem >= 32) ? 0xffffffffu : ((1u << rem) - 1u);
                    }
                }
                int nwl = (M + 31) >> 5;
                for (int w = 0; w < nwl; w++) {
                    unsigned active = __shfl_sync(0xffffffffu, kw, w);
                    while (active) {
                        int b = __ffs(active) - 1;
                        int i = w * 32 + b;
                        unsigned row = (lane < NWMAX) ? smask[i * NWMAX + lane] : 0u;
                        kw &= ~row;                       // rows contain only j>i bits
                        active = __shfl_sync(0xffffffffu, kw, w);
                        active &= (0xfffffffeu << b);     // only bits strictly above b
                    }
                }
                if (lane < NWMAX) skw[lane] = kw;
            }
            __syncthreads();
            for (int t = tid; t < M; t += 512)
                if ((skw[t >> 5] >> (t & 31)) & 1u) emit_row(out, sps[t]);
        } else {
            // ---- mid path: pivot loop in shared (MMASK < M <= CAP) ----
            for (int t = tid; t < M; t += 512) skbyte[t] = 1;
            __syncthreads();
            for (int i = 0; i < M - 1; i++) {
                __syncthreads();
                if (!skbyte[i]) continue;
                float xi1 = sx1[i], yi1 = sy1[i], xi2 = sx2[i], yi2 = sy2[i], ai = sar[i];
                for (int j = i + 1 + tid; j < M; j += 512) {
                    if (!skbyte[j]) continue;
                    float iw = fmaxf(fminf(xi2, sx2[j]) - fmaxf(xi1, sx1[j]), 0.0f);
                    float ih = fmaxf(fminf(yi2, sy2[j]) - fmaxf(yi1, sy1[j]), 0.0f);
                    float inter = iw * ih;
                    float iou = inter / (ai + sar[j] - inter + 1e-6f);
                    if (iou >= IOU_THR) skbyte[j] = 0;
                }
            }
            __syncthreads();
            for (int t = tid; t < M; t += 512)
                if (skbyte[t]) emit_row(out, sps[t]);
        }
    } else {
        // ---- fallback (M > CAP, never expected): global pivot loop over candidate list ----
        for (int t = tid; t < M; t += 512) skbyte[t % (MMASK * NWMAX * 4)] = 0;  // unused slots
        for (int t = tid; t < M && t < MMASK * NWMAX * 4; t += 512) skbyte[t] = 1;
        __syncthreads();
        // for M beyond shared capacity this path would be incorrect; M <= NBOX=8000 < 18432 OK
        for (int i = 0; i < M - 1; i++) {
            __syncthreads();
            if (!skbyte[i]) continue;
            float xi1, yi1, xi2, yi2, ai;
            load_box_r(d_cand[c * NBOX + i], xi1, yi1, xi2, yi2, ai);
            for (int j = i + 1 + tid; j < M; j += 512) {
                if (!skbyte[j]) continue;
                float xj1, yj1, xj2, yj2, aj;
                load_box_r(d_cand[c * NBOX + j], xj1, yj1, xj2, yj2, aj);
                float iw = fmaxf(fminf(xi2, xj2) - fmaxf(xi1, xj1), 0.0f);
                float ih = fmaxf(fminf(yi2, yj2) - fmaxf(yi1, yj1), 0.0f);
                float inter = iw * ih;
                float iou = inter / (ai + aj - inter + 1e-6f);
                if (iou >= IOU_THR) skbyte[j] = 0;
            }
        }
        __syncthreads();
        for (int t = tid; t < M; t += 512)
            if (skbyte[t]) emit_row(out, d_cand[c * NBOX + t]);
    }
}

// ---------------- launch ----------------
extern "C" void kernel_launch(void* const* d_in, const int* in_sizes, int n_in,
                              void* d_out, int out_size) {
    const float* x;
    const float* anchors;
    if (in_sizes[0] == 10) { anchors = (const float*)d_in[0]; x = (const float*)d_in[1]; }
    else                   { x = (const float*)d_in[0]; anchors = (const float*)d_in[1]; }
    float* out = (float*)d_out;

    k_decode <<<(NBOX + 127) / 128, 128>>>(x, anchors, out);
    k_rank   <<<IGROUPS * JC, 256>>>();
    k_scatter<<<(NBOX + 255) / 256, 256>>>();
    k_nms    <<<NCLS, 512>>>(out);
}

// round 7
// speedup vs baseline: 1.8711x; 1.8711x over previous
#include <cuda_runtime.h>

// ---------------- Problem constants ----------------
#define NBOX 8000          // 5 anchors * 40 * 40
#define HW 40
#define NCLS 20
#define CHSTRIDE (HW*HW)   // 1600 floats between channels
#define STRIDEPX 8.0f      // 320 / 40

// rank-sort chunking
#define JC 16
#define CHUNK (NBOX/JC)    // 500
#define IGROUPS 32         // 32 * 256 = 8192 >= 8000

#define MMASK 384          // mask-matrix fast-path capacity (expected M ~ 200)
#define NWMAX 12           // 384/32 words per mask row
#define CAP 768            // shared box capacity (mid path)

// ---------------- Scratch (device globals, no allocation) ----------------
__device__ float              d_dec6[NBOX * 6];       // decoded rows, original index order
__device__ float              d_srt6[NBOX * 6];       // decoded rows, GLOBAL-RANK order
__device__ unsigned long long d_key[NBOX];            // sort key: (~bits(conf))<<32 | idx
__device__ unsigned char      d_code[NBOX];           // valid ? cls : 255
__device__ unsigned           d_partial[JC * NBOX];   // packed: rank | cls_rank<<16
__device__ int                d_cand[NCLS * NBOX];    // per-class global ranks, SORTED by construction
__device__ int                d_cnt[NCLS];

// ---------------- K1: decode (+ zero output) ----------------
__global__ void k_decode(const float* __restrict__ x, const float* __restrict__ anchors,
                         float* __restrict__ out) {
    int i = blockIdx.x * blockDim.x + threadIdx.x;
    if (i < NBOX * 6) out[i] = 0.0f;    // output pre-zero (poisoned before timing)
    if (i >= NBOX) return;

    int a   = i / (HW * HW);
    int rem = i - a * (HW * HW);
    int gy  = rem / HW;
    int gx  = rem - gy * HW;
    int base = ((a * 25) * HW + gy) * HW + gx;

    float t0 = x[base + 0 * CHSTRIDE];
    float t1 = x[base + 1 * CHSTRIDE];
    float t2 = x[base + 2 * CHSTRIDE];
    float t3 = x[base + 3 * CHSTRIDE];
    float t4 = x[base + 4 * CHSTRIDE];

    float tx   = 1.0f / (1.0f + expf(-t0));
    float ty   = 1.0f / (1.0f + expf(-t1));
    float conf = 1.0f / (1.0f + expf(-t4));

    float aw = anchors[a * 2 + 0];
    float ah = anchors[a * 2 + 1];

    float bx = (tx + (float)gx) * STRIDEPX;
    float by = (ty + (float)gy) * STRIDEPX;
    float bw = expf(t2) * aw * STRIDEPX;
    float bh = expf(t3) * ah * STRIDEPX;

    // argmax over class logits (sigmoid monotone; '>' keeps first occurrence like jnp.argmax)
    float best = x[base + 5 * CHSTRIDE];
    int bc = 0;
#pragma unroll
    for (int c = 1; c < NCLS; c++) {
        float t = x[base + (5 + c) * CHSTRIDE];
        if (t > best) { best = t; bc = c; }
    }

    d_dec6[i * 6 + 0] = bx;
    d_dec6[i * 6 + 1] = by;
    d_dec6[i * 6 + 2] = bw;
    d_dec6[i * 6 + 3] = bh;
    d_dec6[i * 6 + 4] = conf;
    d_dec6[i * 6 + 5] = (float)bc;

    // conf in (0,1) positive -> float bits monotone. Descending conf, tie -> ascending idx.
    unsigned u = __float_as_uint(conf);
    d_key[i] = ((unsigned long long)(~u) << 32) | (unsigned long long)(unsigned)i;

    // conf > 0.5  <=>  logit > 0
    d_code[i] = (t4 > 0.0f) ? (unsigned char)bc : (unsigned char)255;
}

// ---------------- K2: chunked rank (global + same-class, packed) ----------------
__global__ void k_rank() {
    __shared__ unsigned long long sk[CHUNK];
    __shared__ unsigned char     sc[CHUNK];
    if (blockIdx.x == 0 && threadIdx.x < NCLS) d_cnt[threadIdx.x] = 0;
    int g = blockIdx.x / JC;
    int c = blockIdx.x - g * JC;
    for (int t = threadIdx.x; t < CHUNK; t += 256) {
        sk[t] = d_key[c * CHUNK + t];
        sc[t] = d_code[c * CHUNK + t];
    }
    __syncthreads();
    int i = g * 256 + threadIdx.x;
    if (i < NBOX) {
        unsigned long long my = d_key[i];
        unsigned char myc = d_code[i];
        unsigned acc = 0;
#pragma unroll 10
        for (int j = 0; j < CHUNK; j++) {
            bool lt = sk[j] < my;
            // packed add: +1 low half, +1<<16 if same class (no carry: per-chunk <= 500)
            acc += lt ? (1u + (((sc[j] == myc) ? 1u : 0u) << 16)) : 0u;
        }
        d_partial[c * NBOX + i] = acc;
    }
}

// ---------------- K2b: scatter -> rank-ordered rows + sorted per-class slots ----------------
__global__ void k_scatter() {
    int i = blockIdx.x * blockDim.x + threadIdx.x;
    if (i >= NBOX) return;
    unsigned s = 0;
#pragma unroll
    for (int c = 0; c < JC; c++) s += d_partial[c * NBOX + i];
    int r  = (int)(s & 0xffffu);   // global rank (unique, 0..7999)
    int rc = (int)(s >> 16);       // rank among same-class valid (unique within class)
#pragma unroll
    for (int k = 0; k < 6; k++) d_srt6[r * 6 + k] = d_dec6[i * 6 + k];
    unsigned char code = d_code[i];
    if (code != (unsigned char)255) {
        d_cand[(int)code * NBOX + rc] = r;   // sorted by construction
        atomicAdd(&d_cnt[code], 1);
    }
}

// helper: box geometry from rank-ordered row r (single indirection)
__device__ __forceinline__ void load_box_r(int r, float& x1, float& y1,
                                           float& x2, float& y2, float& ar) {
    float cx = d_srt6[r * 6 + 0];
    float cy = d_srt6[r * 6 + 1];
    float w  = d_srt6[r * 6 + 2];
    float h  = d_srt6[r * 6 + 3];
    x1 = cx - 0.5f * w; y1 = cy - 0.5f * h;
    x2 = cx + 0.5f * w; y2 = cy + 0.5f * h;
    ar = fabsf((x2 - x1) * (y2 - y1));
}

__device__ __forceinline__ void emit_row(float* out, int r) {
#pragma unroll
    for (int k = 0; k < 6; k++) out[6 * r + k] = d_srt6[6 * r + k];
}

// IoU >= 0.5 test without division (exact comparison; ref rounds a division first,
// boundary flip window ~1ulp — negligible)
__device__ __forceinline__ bool sup_test(float xi1, float yi1, float xi2, float yi2, float ai,
                                         float xj1, float yj1, float xj2, float yj2, float aj) {
    float iw = fmaxf(fminf(xi2, xj2) - fmaxf(xi1, xj1), 0.0f);
    float ih = fmaxf(fminf(yi2, yj2) - fmaxf(yi1, yj1), 0.0f);
    float inter = iw * ih;
    float denom = ai + aj - inter + 1e-6f;
    return 2.0f * inter >= denom;
}

// ---------------- K3: per-class NMS (pre-sorted candidates) + output rows ----------------
__global__ void k_nms(float* __restrict__ out) {
    __shared__ int      sps[CAP];
    __shared__ float    sx1[CAP], sy1[CAP], sx2[CAP], sy2[CAP], sar[CAP];
    __shared__ unsigned smask[MMASK * NWMAX];   // suppression bit-matrix
    __shared__ unsigned srow[NWMAX];            // "row i has any suppression" bitmap
    __shared__ unsigned skw[NWMAX];             // final keep words

    int c    = blockIdx.x;
    int tid  = threadIdx.x;
    int lane = tid & 31;
    int M    = d_cnt[c];
    if (M == 0) return;

    if (M <= MMASK) {
        // ---- load sorted candidates + boxes ----
        if (tid < NWMAX) srow[tid] = 0;
        for (int t = tid; t < M; t += 512) {
            int r = d_cand[c * NBOX + t];
            sps[t] = r;
            float x1, y1, x2, y2, ar;
            load_box_r(r, x1, y1, x2, y2, ar);
            sx1[t] = x1; sy1[t] = y1; sx2[t] = x2; sy2[t] = y2; sar[t] = ar;
        }
        __syncthreads();

        // ---- parallel suppression-mask fill (no division) ----
        int nw = (M + 31) >> 5;
        for (int task = tid; task < M * nw; task += 512) {
            int i  = task / nw;
            int wq = task - i * nw;
            unsigned bits = 0;
            if ((wq * 32 + 31) > i) {
                float xi1 = sx1[i], yi1 = sy1[i], xi2 = sx2[i], yi2 = sy2[i], ai = sar[i];
                int j0 = wq * 32;
                int jend = min(j0 + 32, M);
#pragma unroll 4
                for (int j = max(j0, i + 1); j < jend; j++) {
                    if (sup_test(xi1, yi1, xi2, yi2, ai,
                                 sx1[j], sy1[j], sx2[j], sy2[j], sar[j]))
                        bits |= 1u << (j - j0);
                }
            }
            smask[i * NWMAX + wq] = bits;
            if (bits) atomicOr(&srow[i >> 5], 1u << (i & 31));
        }
        __syncthreads();

        // ---- serial greedy sweep, warp 0: only pivots that suppress something ----
        if (tid < 32) {
            unsigned kw = 0;
            if (lane < NWMAX) {
                int lo = lane * 32;
                if (lo < M) {
                    int rem = M - lo;
                    kw = (rem >= 32) ? 0xffffffffu : ((1u << rem) - 1u);
                }
            }
            for (int w = 0; w < nw; w++) {
                unsigned rw = srow[w];                          // rows with work
                unsigned active = __shfl_sync(0xffffffffu, kw, w) & rw;
                while (active) {
                    int b = __ffs(active) - 1;
                    int i = w * 32 + b;
                    unsigned row = (lane < NWMAX) ? smask[i * NWMAX + lane] : 0u;
                    kw &= ~row;                                 // rows contain only j>i bits
                    active = __shfl_sync(0xffffffffu, kw, w) & rw;
                    active &= (0xfffffffeu << b);               // only bits strictly above b
                }
            }
            if (lane < NWMAX) skw[lane] = kw;
        }
        __syncthreads();
        for (int t = tid; t < M; t += 512)
            if ((skw[t >> 5] >> (t & 31)) & 1u) emit_row(out, sps[t]);
    } else if (M <= CAP) {
        // ---- mid path: pivot loop in shared ----
        unsigned char* skbyte = (unsigned char*)smask;   // reuse mask region (>= CAP bytes)
        for (int t = tid; t < M; t += 512) {
            int r = d_cand[c * NBOX + t];
            sps[t] = r;
            float x1, y1, x2, y2, ar;
            load_box_r(r, x1, y1, x2, y2, ar);
            sx1[t] = x1; sy1[t] = y1; sx2[t] = x2; sy2[t] = y2; sar[t] = ar;
            skbyte[t] = 1;
        }
        __syncthreads();
        for (int i = 0; i < M - 1; i++) {
            __syncthreads();
            if (!skbyte[i]) continue;
            float xi1 = sx1[i], yi1 = sy1[i], xi2 = sx2[i], yi2 = sy2[i], ai = sar[i];
            for (int j = i + 1 + tid; j < M; j += 512) {
                if (!skbyte[j]) continue;
                if (sup_test(xi1, yi1, xi2, yi2, ai,
                             sx1[j], sy1[j], sx2[j], sy2[j], sar[j]))
                    skbyte[j] = 0;
            }
        }
        __syncthreads();
        for (int t = tid; t < M; t += 512)
            if (skbyte[t]) emit_row(out, sps[t]);
    } else {
        // ---- fallback (M > CAP, never expected): global pivot loop ----
        unsigned char* skbyte = (unsigned char*)sx1;     // 768*5*4 = 15360 bytes >= NBOX
        for (int t = tid; t < M; t += 512) skbyte[t] = 1;
        __syncthreads();
        for (int i = 0; i < M - 1; i++) {
            __syncthreads();
            if (!skbyte[i]) continue;
            float xi1, yi1, xi2, yi2, ai;
            load_box_r(d_cand[c * NBOX + i], xi1, yi1, xi2, yi2, ai);
            for (int j = i + 1 + tid; j < M; j += 512) {
                if (!skbyte[j]) continue;
                float xj1, yj1, xj2, yj2, aj;
                load_box_r(d_cand[c * NBOX + j], xj1, yj1, xj2, yj2, aj);
                if (sup_test(xi1, yi1, xi2, yi2, ai, xj1, yj1, xj2, yj2, aj))
                    skbyte[j] = 0;
            }
        }
        __syncthreads();
        for (int t = tid; t < M; t += 512)
            if (skbyte[t]) emit_row(out, d_cand[c * NBOX + t]);
    }
}

// ---------------- launch ----------------
extern "C" void kernel_launch(void* const* d_in, const int* in_sizes, int n_in,
                              void* d_out, int out_size) {
    const float* x;
    const float* anchors;
    if (in_sizes[0] == 10) { anchors = (const float*)d_in[0]; x = (const float*)d_in[1]; }
    else                   { x = (const float*)d_in[0]; anchors = (const float*)d_in[1]; }
    float* out = (float*)d_out;

    k_decode <<<(NBOX * 6 + 255) / 256, 256>>>(x, anchors, out);
    k_rank   <<<IGROUPS * JC, 256>>>();
    k_scatter<<<(NBOX + 255) / 256, 256>>>();
    k_nms    <<<NCLS, 512>>>(out);
}

// round 8
// speedup vs baseline: 2.9379x; 1.5701x over previous
#include <cuda_runtime.h>

// ---------------- Problem constants ----------------
#define NBOX 8000          // 5 anchors * 40 * 40
#define HW 40
#define NCLS 20
#define CHSTRIDE (HW*HW)   // 1600 floats between channels
#define STRIDEPX 8.0f      // 320 / 40

#define JC 16
#define CHUNKMAX 500       // ceil(NVmax/JC) = 8000/16
#define IGROUPS 32         // 32*256 = 8192 >= NV

#define MMASK 384          // mask-matrix fast-path capacity (expected M ~ 200)
#define NWMAX 12           // 384/32 words per mask row
#define CAP 768            // shared box capacity (mid path)

// ---------------- Scratch (device globals, no allocation) ----------------
__device__ float              d_dec6[NBOX * 6];       // decoded rows, original index order
__device__ float              d_srt6[NBOX * 6];       // decoded rows, rank order (valid ranks only)
__device__ float              d_geo[NBOX * 8];        // per-rank: x1,y1,x2,y2,area,pad (32B)
__device__ unsigned long long d_vkey[NBOX];           // valid-compacted keys
__device__ unsigned char      d_vcode[NBOX];          // valid-compacted class
__device__ int                d_vidx[NBOX];           // valid-compacted original index
__device__ int                d_nv;                   // number of valid boxes
__device__ unsigned           d_partial[JC * NBOX];   // packed: rank | cls_rank<<16
__device__ int                d_cand[NCLS * NBOX];    // per-class ranks, SORTED by construction
__device__ int                d_cnt[NCLS];

// ---------------- K1: decode + valid compaction + zero output ----------------
__global__ void k_decode(const float* __restrict__ x, const float* __restrict__ anchors,
                         float* __restrict__ out) {
    int i = blockIdx.x * blockDim.x + threadIdx.x;
    if (i < NBOX * 6) out[i] = 0.0f;      // output pre-zero (poisoned before timing)
    if (i < NCLS) d_cnt[i] = 0;
    if (i >= NBOX) return;

    int a   = i / (HW * HW);
    int rem = i - a * (HW * HW);
    int gy  = rem / HW;
    int gx  = rem - gy * HW;
    int base = ((a * 25) * HW + gy) * HW + gx;

    float t0 = x[base + 0 * CHSTRIDE];
    float t1 = x[base + 1 * CHSTRIDE];
    float t2 = x[base + 2 * CHSTRIDE];
    float t3 = x[base + 3 * CHSTRIDE];
    float t4 = x[base + 4 * CHSTRIDE];

    float tx   = 1.0f / (1.0f + expf(-t0));
    float ty   = 1.0f / (1.0f + expf(-t1));
    float conf = 1.0f / (1.0f + expf(-t4));

    float aw = anchors[a * 2 + 0];
    float ah = anchors[a * 2 + 1];

    float bx = (tx + (float)gx) * STRIDEPX;
    float by = (ty + (float)gy) * STRIDEPX;
    float bw = expf(t2) * aw * STRIDEPX;
    float bh = expf(t3) * ah * STRIDEPX;

    // argmax over class logits (sigmoid monotone; '>' keeps first occurrence like jnp.argmax)
    float best = x[base + 5 * CHSTRIDE];
    int bc = 0;
#pragma unroll
    for (int c = 1; c < NCLS; c++) {
        float t = x[base + (5 + c) * CHSTRIDE];
        if (t > best) { best = t; bc = c; }
    }

    d_dec6[i * 6 + 0] = bx;
    d_dec6[i * 6 + 1] = by;
    d_dec6[i * 6 + 2] = bw;
    d_dec6[i * 6 + 3] = bh;
    d_dec6[i * 6 + 4] = conf;
    d_dec6[i * 6 + 5] = (float)bc;

    // valid (conf>0.5 <=> logit>0): append to compacted list.
    // Slot order is nondeterministic but ranks below are value-based -> deterministic output.
    if (t4 > 0.0f) {
        int slot = atomicAdd(&d_nv, 1);
        unsigned u = __float_as_uint(conf);
        d_vkey[slot]  = ((unsigned long long)(~u) << 32) | (unsigned long long)(unsigned)i;
        d_vcode[slot] = (unsigned char)bc;
        d_vidx[slot]  = i;
    }
}

// ---------------- K2: chunked rank over VALID boxes only ----------------
__global__ void k_rank() {
    __shared__ unsigned long long sk[CHUNKMAX];
    __shared__ unsigned char     sc[CHUNKMAX];
    int NV = d_nv;
    int CS = (NV + JC - 1) / JC;                 // dynamic chunk size (<= 500)
    int g = blockIdx.x / JC;
    int c = blockIdx.x - g * JC;
    int j0 = c * CS;
    int cnt = NV - j0; if (cnt > CS) cnt = CS; if (cnt < 0) cnt = 0;
    for (int t = threadIdx.x; t < cnt; t += 256) {
        sk[t] = d_vkey[j0 + t];
        sc[t] = d_vcode[j0 + t];
    }
    __syncthreads();
    int i = g * 256 + threadIdx.x;
    if (i < NV) {
        unsigned long long my = d_vkey[i];
        unsigned char myc = d_vcode[i];
        unsigned acc = 0;
#pragma unroll 4
        for (int j = 0; j < cnt; j++) {
            bool lt = sk[j] < my;
            acc += lt ? (1u + (((sc[j] == myc) ? 1u : 0u) << 16)) : 0u;
        }
        d_partial[c * NBOX + i] = acc;
    }
}

// ---------------- K2b: scatter -> rank rows + geometry + sorted class slots ----------------
__global__ void k_scatter() {
    int i = blockIdx.x * blockDim.x + threadIdx.x;
    int NV = d_nv;
    if (i >= NV) return;
    unsigned s = 0;
#pragma unroll
    for (int c = 0; c < JC; c++) s += d_partial[c * NBOX + i];
    int r  = (int)(s & 0xffffu);   // rank among valid == global rank (valid sort above invalid)
    int rc = (int)(s >> 16);       // rank among same-class valid
    int orig = d_vidx[i];
    float cx = d_dec6[orig * 6 + 0];
    float cy = d_dec6[orig * 6 + 1];
    float w  = d_dec6[orig * 6 + 2];
    float h  = d_dec6[orig * 6 + 3];
    d_srt6[r * 6 + 0] = cx;
    d_srt6[r * 6 + 1] = cy;
    d_srt6[r * 6 + 2] = w;
    d_srt6[r * 6 + 3] = h;
    d_srt6[r * 6 + 4] = d_dec6[orig * 6 + 4];
    d_srt6[r * 6 + 5] = d_dec6[orig * 6 + 5];
    float x1 = cx - 0.5f * w, y1 = cy - 0.5f * h;
    float x2 = cx + 0.5f * w, y2 = cy + 0.5f * h;
    float4* g4 = (float4*)&d_geo[r * 8];
    *g4 = make_float4(x1, y1, x2, y2);
    d_geo[r * 8 + 4] = fabsf((x2 - x1) * (y2 - y1));
    int cls = (int)d_vcode[i];
    d_cand[cls * NBOX + rc] = r;
    atomicAdd(&d_cnt[cls], 1);
}

__device__ __forceinline__ void emit_row(float* out, int r) {
#pragma unroll
    for (int k = 0; k < 6; k++) out[6 * r + k] = d_srt6[6 * r + k];
}

// IoU >= 0.5 <=> 2*inter >= union (division-free)
__device__ __forceinline__ bool sup_test(float xi1, float yi1, float xi2, float yi2, float ai,
                                         float xj1, float yj1, float xj2, float yj2, float aj) {
    float iw = fmaxf(fminf(xi2, xj2) - fmaxf(xi1, xj1), 0.0f);
    float ih = fmaxf(fminf(yi2, yj2) - fmaxf(yi1, yj1), 0.0f);
    float inter = iw * ih;
    float denom = ai + aj - inter + 1e-6f;
    return 2.0f * inter >= denom;
}

// ---------------- K3: per-class NMS + output rows ----------------
__global__ void k_nms(float* __restrict__ out) {
    __shared__ int      sps[CAP];
    __shared__ float    sx1[CAP], sy1[CAP], sx2[CAP], sy2[CAP], sar[CAP];
    __shared__ unsigned smask[MMASK * NWMAX];
    __shared__ unsigned srow[NWMAX];
    __shared__ unsigned skw[NWMAX];

    int c    = blockIdx.x;
    int tid  = threadIdx.x;
    int lane = tid & 31;
    int warp = tid >> 5;

    if (c == 0 && tid == 0) d_nv = 0;   // reset for next graph replay (this replay done with it)

    int M = d_cnt[c];
    if (M == 0) return;

    if (M <= MMASK) {
        // ---- load candidates + precomputed geometry ----
        if (tid < NWMAX) srow[tid] = 0;
        for (int t = tid; t < M; t += 512) {
            int r = d_cand[c * NBOX + t];
            sps[t] = r;
            float4 g4 = *(const float4*)&d_geo[r * 8];
            sx1[t] = g4.x; sy1[t] = g4.y; sx2[t] = g4.z; sy2[t] = g4.w;
            sar[t] = d_geo[r * 8 + 4];
        }
        __syncthreads();

        // ---- ballot mask fill: one warp per row ----
        int nw = (M + 31) >> 5;
        for (int i = warp; i < M; i += 16) {
            float xi1 = sx1[i], yi1 = sy1[i], xi2 = sx2[i], yi2 = sy2[i], ai = sar[i];
            int wq0 = (i + 1) >> 5;
            unsigned rowany = 0;
            if (lane == 0)
                for (int q = 0; q < wq0; q++) smask[i * NWMAX + q] = 0;
            for (int wq = wq0; wq < nw; wq++) {
                int j = (wq << 5) + lane;
                bool s = (j > i) && (j < M) &&
                         sup_test(xi1, yi1, xi2, yi2, ai,
                                  sx1[j], sy1[j], sx2[j], sy2[j], sar[j]);
                unsigned bits = __ballot_sync(0xffffffffu, s);
                if (lane == 0) smask[i * NWMAX + wq] = bits;
                rowany |= bits;
            }
            if (lane == 0 && rowany) atomicOr(&srow[i >> 5], 1u << (i & 31));
        }
        __syncthreads();

        // ---- single-thread register sweep ----
        if (tid == 0) {
            unsigned kw[NWMAX];
#pragma unroll
            for (int q = 0; q < NWMAX; q++) {
                int lo = q * 32;
                unsigned v = 0;
                if (lo < M) {
                    int rem = M - lo;
                    v = (rem >= 32) ? 0xffffffffu : ((1u << rem) - 1u);
                }
                kw[q] = v;
            }
            for (int w = 0; w < nw; w++) {
                unsigned active = kw[w] & srow[w];
                while (active) {
                    int b = __ffs(active) - 1;
                    int i = w * 32 + b;
#pragma unroll
                    for (int q = 0; q < NWMAX; q++)
                        kw[q] &= ~smask[i * NWMAX + q];   // row has only j>i bits; q>=nw: kw[q]=0
                    active = kw[w] & srow[w] & (0xfffffffeu << b);
                }
            }
#pragma unroll
            for (int q = 0; q < NWMAX; q++) skw[q] = kw[q];
        }
        __syncthreads();
        for (int t = tid; t < M; t += 512)
            if ((skw[t >> 5] >> (t & 31)) & 1u) emit_row(out, sps[t]);
    } else if (M <= CAP) {
        // ---- mid path: pivot loop in shared ----
        unsigned char* skbyte = (unsigned char*)smask;
        for (int t = tid; t < M; t += 512) {
            int r = d_cand[c * NBOX + t];
            sps[t] = r;
            float4 g4 = *(const float4*)&d_geo[r * 8];
            sx1[t] = g4.x; sy1[t] = g4.y; sx2[t] = g4.z; sy2[t] = g4.w;
            sar[t] = d_geo[r * 8 + 4];
            skbyte[t] = 1;
        }
        __syncthreads();
        for (int i = 0; i < M - 1; i++) {
            __syncthreads();
            if (!skbyte[i]) continue;
            float xi1 = sx1[i], yi1 = sy1[i], xi2 = sx2[i], yi2 = sy2[i], ai = sar[i];
            for (int j = i + 1 + tid; j < M; j += 512) {
                if (!skbyte[j]) continue;
                if (sup_test(xi1, yi1, xi2, yi2, ai,
                             sx1[j], sy1[j], sx2[j], sy2[j], sar[j]))
                    skbyte[j] = 0;
            }
        }
        __syncthreads();
        for (int t = tid; t < M; t += 512)
            if (skbyte[t]) emit_row(out, sps[t]);
    } else {
        // ---- fallback (M > CAP, never expected): global pivot loop ----
        unsigned char* skbyte = (unsigned char*)sx1;     // 15360 bytes >= NBOX? 8000 ✓
        for (int t = tid; t < M; t += 512) skbyte[t] = 1;
        __syncthreads();
        for (int i = 0; i < M - 1; i++) {
            __syncthreads();
            if (!skbyte[i]) continue;
            int ri = d_cand[c * NBOX + i];
            float4 gi = *(const float4*)&d_geo[ri * 8];
            float ai = d_geo[ri * 8 + 4];
            for (int j = i + 1 + tid; j < M; j += 512) {
                if (!skbyte[j]) continue;
                int rj = d_cand[c * NBOX + j];
                float4 gj = *(const float4*)&d_geo[rj * 8];
                float aj = d_geo[rj * 8 + 4];
                if (sup_test(gi.x, gi.y, gi.z, gi.w, ai, gj.x, gj.y, gj.z, gj.w, aj))
                    skbyte[j] = 0;
            }
        }
        __syncthreads();
        for (int t = tid; t < M; t += 512)
            if (skbyte[t]) emit_row(out, d_cand[c * NBOX + t]);
    }
}

// ---------------- launch ----------------
extern "C" void kernel_launch(void* const* d_in, const int* in_sizes, int n_in,
                              void* d_out, int out_size) {
    const float* x;
    const float* anchors;
    if (in_sizes[0] == 10) { anchors = (const float*)d_in[0]; x = (const float*)d_in[1]; }
    else                   { x = (const float*)d_in[0]; anchors = (const float*)d_in[1]; }
    float* out = (float*)d_out;

    k_decode <<<(NBOX * 6 + 255) / 256, 256>>>(x, anchors, out);
    k_rank   <<<IGROUPS * JC, 256>>>();
    k_scatter<<<(NBOX + 255) / 256, 256>>>();
    k_nms    <<<NCLS, 512>>>(out);
}